// round 14
// baseline (speedup 1.0000x reference)
#include <cuda_runtime.h>
#include <cuda_fp16.h>
#include <cstdint>

#define N_LEVELS 16
#define LOG2_T 19
#define HASH_MASK ((1u << LOG2_T) - 1u)
#define P0 73856093u
#define P1 19349663u
#define P2 83492791u

// floor(16 * 2^(l/3)) through the reference fp32 chain (verified in R1).
__device__ constexpr float c_resf[N_LEVELS] = {
    16.f, 20.f, 25.f, 32.f, 40.f, 50.f, 64.f, 80.f,
    101.f, 128.f, 161.f, 203.f, 256.f, 322.f, 406.f, 512.f
};

// Dense levels 0..8: fp16 2x2 yz-corner-block tables (16B entries).
#define N_DENSE 9
__device__ constexpr int c_sy[N_DENSE]  = {17, 21, 26, 33, 41, 51, 65, 81, 102};
__device__ constexpr int c_sx[N_DENSE]  = {289, 441, 676, 1089, 1681, 2601, 4225, 6561, 10404};
__device__ constexpr int c_OFF[N_DENSE] = {
    0, 5202, 14904, 33156, 70182, 140784, 276036, 554886, 1092888
};
#define DENSE_TOTAL 2164500
__device__ uint4 g_dense[DENSE_TOTAL];       // 34.6 MB, L2-resident

// Corner tables: C[cx][cy][cz], dims (R+2)^3, packed fp16x2 per corner.
__device__ constexpr int c_cd[N_DENSE]   = {18, 22, 27, 34, 42, 52, 66, 82, 103};
__device__ constexpr int c_COFF[N_DENSE] = {
    0, 5832, 16480, 36163, 75467, 149555, 290163, 577659, 1129027
};
#define CORNER_TOTAL 2221754
__device__ unsigned g_corner[CORNER_TOTAL];  // 8.9 MB (transient)

// sync counters: [0]=stage1 done, [1]=stage2 done. Reset per launch (memset node).
__device__ unsigned g_sync[2];

// magic-number unsigned division: exact for u < 2^22, d <= 130
constexpr unsigned long long magic(unsigned d) { return ((1ULL << 40) / d) + 1ULL; }
__device__ constexpr unsigned long long c_mcd[N_DENSE] = {
    magic(18), magic(22), magic(27), magic(34), magic(42),
    magic(52), magic(66), magic(82), magic(103)
};
__device__ constexpr unsigned long long c_msy[N_DENSE] = {
    magic(17), magic(21), magic(26), magic(33), magic(41),
    magic(51), magic(65), magic(81), magic(102)
};
__device__ __forceinline__ unsigned mdiv(unsigned u, unsigned long long M) {
    return (unsigned)(((unsigned long long)u * M) >> 40);
}

__device__ __forceinline__ unsigned pack_h2(float a, float b) {
    __half2 h = __floats2half2_rn(a, b);
    return *reinterpret_cast<unsigned*>(&h);
}

__device__ __forceinline__ unsigned poll_cg(const unsigned* p) {
    unsigned v;
    asm volatile("ld.global.cg.u32 %0, [%1];" : "=r"(v) : "l"(p));
    return v;
}

// One prepass block per SM: guaranteed wave-1 resident at any occupancy >= 1.
#define PRE_BLOCKS 148
#define PRE_THREADS (PRE_BLOCKS * 256)

__global__ void __launch_bounds__(256, 2) hashenc_fused(
    const float* __restrict__ x,
    const float* __restrict__ emb,
    float* __restrict__ out,
    int B)
{
    const int tidb = threadIdx.x;

    // ================= inline prepass (blocks 0..147) =================
    if (blockIdx.x < PRE_BLOCKS) {
        const unsigned base = blockIdx.x * 256u + (unsigned)tidb;

        // ---- stage 1: gather each corner once (batches of 4 for MLP) ----
        for (unsigned b0 = base; b0 < CORNER_TOTAL; b0 += 4u * PRE_THREADS) {
            unsigned hh[4]; int lv[4]; bool ok[4];
            #pragma unroll
            for (int k = 0; k < 4; k++) {
                unsigned idx = b0 + (unsigned)k * PRE_THREADS;
                ok[k] = (idx < CORNER_TOTAL);
                unsigned ci = ok[k] ? idx : 0u;
                int l = 0;
                #pragma unroll
                for (int m = 1; m < N_DENSE; m++)
                    if (ci >= (unsigned)c_COFF[m]) l = m;
                unsigned loc = ci - (unsigned)c_COFF[l];
                unsigned t  = mdiv(loc, c_mcd[l]);
                unsigned cz = loc - t * (unsigned)c_cd[l];
                unsigned cx = mdiv(t, c_mcd[l]);
                unsigned cy = t - cx * (unsigned)c_cd[l];
                hh[k] = ((cx * P0) ^ (cy * P1) ^ (cz * P2)) & HASH_MASK;
                lv[k] = l;
            }
            float2 e[4];
            #pragma unroll
            for (int k = 0; k < 4; k++)
                e[k] = __ldg((const float2*)emb + ((size_t)lv[k] << LOG2_T) + hh[k]);
            #pragma unroll
            for (int k = 0; k < 4; k++)
                if (ok[k])
                    g_corner[b0 + (unsigned)k * PRE_THREADS] = pack_h2(e[k].x, e[k].y);
        }

        __threadfence();
        __syncthreads();
        if (tidb == 0) {
            atomicAdd(&g_sync[0], 1u);
            while (poll_cg(&g_sync[0]) < PRE_BLOCKS) __nanosleep(64);
        }
        __syncthreads();
        __threadfence();

        // ---- stage 2: assemble 2x2 yz-blocks ----
        for (unsigned b0 = base; b0 < DENSE_TOTAL; b0 += 4u * PRE_THREADS) {
            unsigned cb[4], dd[4]; const unsigned* Cb[4]; bool ok[4];
            #pragma unroll
            for (int k = 0; k < 4; k++) {
                unsigned idx = b0 + (unsigned)k * PRE_THREADS;
                ok[k] = (idx < DENSE_TOTAL);
                unsigned ci = ok[k] ? idx : 0u;
                int l = 0;
                #pragma unroll
                for (int m = 1; m < N_DENSE; m++)
                    if (ci >= (unsigned)c_OFF[m]) l = m;
                unsigned loc = ci - (unsigned)c_OFF[l];
                unsigned sy = (unsigned)c_sy[l];
                unsigned t  = mdiv(loc, c_msy[l]);
                unsigned bz = loc - t * sy;
                unsigned cx = mdiv(t, c_msy[l]);
                unsigned by = t - cx * sy;
                unsigned d = (unsigned)c_cd[l];
                dd[k] = d;
                Cb[k] = g_corner + c_COFF[l];
                cb[k] = (cx * d + by) * d + bz;
            }
            uint4 q[4];
            #pragma unroll
            for (int k = 0; k < 4; k++) {
                q[k].x = __ldg(Cb[k] + cb[k]);
                q[k].y = __ldg(Cb[k] + cb[k] + 1);
                q[k].z = __ldg(Cb[k] + cb[k] + dd[k]);
                q[k].w = __ldg(Cb[k] + cb[k] + dd[k] + 1);
            }
            #pragma unroll
            for (int k = 0; k < 4; k++)
                if (ok[k]) g_dense[b0 + (unsigned)k * PRE_THREADS] = q[k];
        }

        __threadfence();
        __syncthreads();
        if (tidb == 0) atomicAdd(&g_sync[1], 1u);
    }

    // ================= main work =================
    const int lane = tidb & 31;
    const int warp = tidb >> 5;
    const int i = blockIdx.x * 256 + tidb;
    const int warpBase = i - lane;
    if (warpBase >= B) return;               // sm_70+: exited threads ok at barriers
    const bool active = (i < B);
    const int ii = active ? i : (B - 1);

    float px = x[3 * ii + 0];
    float py = x[3 * ii + 1];
    float pz = x[3 * ii + 2];
    px = fminf(fmaxf(px, -1.0f), 1.0f);
    py = fminf(fmaxf(py, -1.0f), 1.0f);
    pz = fminf(fmaxf(pz, -1.0f), 1.0f);

    float o[2 * N_LEVELS];

    // ---------- phase 1: hashed levels 9..15 (independent of g_dense) ----------
    #pragma unroll
    for (int l = N_DENSE; l < N_LEVELS; l++) {
        const float hres = 0.5f * c_resf[l];
        float tx = fmaf(px, hres, hres);
        float ty = fmaf(py, hres, hres);
        float tz = fmaf(pz, hres, hres);
        float fbx = floorf(tx), fby = floorf(ty), fbz = floorf(tz);
        int bx = (int)fbx, by = (int)fby, bz = (int)fbz;
        float wx = tx - fbx, wy = ty - fby, wz = tz - fbz;
        float wx0 = 1.0f - wx, wy0 = 1.0f - wy, wz0 = 1.0f - wz;

        unsigned hx0 = (unsigned)bx * P0, hx1 = hx0 + P0;
        unsigned hy0 = (unsigned)by * P1, hy1 = hy0 + P1;
        unsigned hz0 = (unsigned)bz * P2, hz1 = hz0 + P2;

        unsigned h0 = (hx0 ^ hy0 ^ hz0) & HASH_MASK;
        unsigned h1 = (hx0 ^ hy0 ^ hz1) & HASH_MASK;
        unsigned h2 = (hx0 ^ hy1 ^ hz0) & HASH_MASK;
        unsigned h3 = (hx0 ^ hy1 ^ hz1) & HASH_MASK;
        unsigned h4 = (hx1 ^ hy0 ^ hz0) & HASH_MASK;
        unsigned h5 = (hx1 ^ hy0 ^ hz1) & HASH_MASK;
        unsigned h6 = (hx1 ^ hy1 ^ hz0) & HASH_MASK;
        unsigned h7 = (hx1 ^ hy1 ^ hz1) & HASH_MASK;

        const float2* tbl = (const float2*)emb + ((size_t)l << LOG2_T);
        float2 e0 = __ldg(tbl + h0);
        float2 e1 = __ldg(tbl + h1);
        float2 e2 = __ldg(tbl + h2);
        float2 e3 = __ldg(tbl + h3);
        float2 e4 = __ldg(tbl + h4);
        float2 e5 = __ldg(tbl + h5);
        float2 e6 = __ldg(tbl + h6);
        float2 e7 = __ldg(tbl + h7);

        float cxy00 = wx0 * wy0;
        float cxy01 = wx0 * wy;
        float cxy10 = wx  * wy0;
        float cxy11 = wx  * wy;

        float c0 = cxy00 * wz0, c1 = cxy00 * wz;
        float c2 = cxy01 * wz0, c3 = cxy01 * wz;
        float c4 = cxy10 * wz0, c5 = cxy10 * wz;
        float c6 = cxy11 * wz0, c7 = cxy11 * wz;

        float a0, a1;
        a0 = c0 * e0.x;            a1 = c0 * e0.y;
        a0 = fmaf(c1, e1.x, a0);   a1 = fmaf(c1, e1.y, a1);
        a0 = fmaf(c2, e2.x, a0);   a1 = fmaf(c2, e2.y, a1);
        a0 = fmaf(c3, e3.x, a0);   a1 = fmaf(c3, e3.y, a1);
        a0 = fmaf(c4, e4.x, a0);   a1 = fmaf(c4, e4.y, a1);
        a0 = fmaf(c5, e5.x, a0);   a1 = fmaf(c5, e5.y, a1);
        a0 = fmaf(c6, e6.x, a0);   a1 = fmaf(c6, e6.y, a1);
        a0 = fmaf(c7, e7.x, a0);   a1 = fmaf(c7, e7.y, a1);

        o[2 * l + 0] = a0;
        o[2 * l + 1] = a1;
    }

    // ---------- wait for prepass stage 2 before touching g_dense ----------
    if (tidb == 0) {
        while (poll_cg(&g_sync[1]) < PRE_BLOCKS) __nanosleep(128);
    }
    __syncthreads();
    __threadfence();

    // ---------- phase 2: dense levels 0..8 ----------
    #pragma unroll
    for (int l = 0; l < N_DENSE; l++) {
        const float hres = 0.5f * c_resf[l];
        float tx = fmaf(px, hres, hres);
        float ty = fmaf(py, hres, hres);
        float tz = fmaf(pz, hres, hres);
        float fbx = floorf(tx), fby = floorf(ty), fbz = floorf(tz);
        int bx = (int)fbx, by = (int)fby, bz = (int)fbz;
        float wx = tx - fbx, wy = ty - fby, wz = tz - fbz;
        float wx0 = 1.0f - wx, wy0 = 1.0f - wy, wz0 = 1.0f - wz;

        const int sy = c_sy[l];
        const int sx = c_sx[l];
        const uint4* dp = g_dense + c_OFF[l];
        int base = bx * sx + by * sy + bz;
        uint4 q0 = __ldg(dp + base);
        uint4 q1 = __ldg(dp + base + sx);

        float wyz00 = wy0 * wz0;
        float wyz01 = wy0 * wz;
        float wyz10 = wy  * wz0;
        float wyz11 = wy  * wz;

        float2 f00 = __half22float2(*reinterpret_cast<__half2*>(&q0.x));
        float2 f01 = __half22float2(*reinterpret_cast<__half2*>(&q0.y));
        float2 f10 = __half22float2(*reinterpret_cast<__half2*>(&q0.z));
        float2 f11 = __half22float2(*reinterpret_cast<__half2*>(&q0.w));
        float v0x = wyz00 * f00.x;           float v0y = wyz00 * f00.y;
        v0x = fmaf(wyz01, f01.x, v0x);       v0y = fmaf(wyz01, f01.y, v0y);
        v0x = fmaf(wyz10, f10.x, v0x);       v0y = fmaf(wyz10, f10.y, v0y);
        v0x = fmaf(wyz11, f11.x, v0x);       v0y = fmaf(wyz11, f11.y, v0y);

        float2 g00 = __half22float2(*reinterpret_cast<__half2*>(&q1.x));
        float2 g01 = __half22float2(*reinterpret_cast<__half2*>(&q1.y));
        float2 g10 = __half22float2(*reinterpret_cast<__half2*>(&q1.z));
        float2 g11 = __half22float2(*reinterpret_cast<__half2*>(&q1.w));
        float v1x = wyz00 * g00.x;           float v1y = wyz00 * g00.y;
        v1x = fmaf(wyz01, g01.x, v1x);       v1y = fmaf(wyz01, g01.y, v1y);
        v1x = fmaf(wyz10, g10.x, v1x);       v1y = fmaf(wyz10, g10.y, v1y);
        v1x = fmaf(wyz11, g11.x, v1x);       v1y = fmaf(wyz11, g11.y, v1y);

        o[2 * l + 0] = fmaf(wx, v1x, wx0 * v0x);
        o[2 * l + 1] = fmaf(wx, v1y, wx0 * v0y);
    }

    // ---- coalesced output via warp-level smem transpose (deferred, batched) ----
    __shared__ float4 sbuf[8 * 32 * 9];
    float4* wb = sbuf + warp * (32 * 9);

    if (warpBase + 32 <= B) {
        #pragma unroll
        for (int s = 0; s < 8; s++)
            wb[lane * 9 + s] = make_float4(o[4*s+0], o[4*s+1], o[4*s+2], o[4*s+3]);
        __syncwarp();
        float4* ob = (float4*)out + (size_t)warpBase * 8;
        #pragma unroll
        for (int k = 0; k < 8; k++) {
            int r = k * 4 + (lane >> 3);
            int s = lane & 7;
            __stcs(ob + k * 32 + lane, wb[r * 9 + s]);   // streaming: protect L2 hot set
        }
    } else if (active) {
        float4* po = (float4*)(out + (size_t)i * (2 * N_LEVELS));
        #pragma unroll
        for (int s = 0; s < 8; s++)
            __stcs(po + s, make_float4(o[4*s+0], o[4*s+1], o[4*s+2], o[4*s+3]));
    }
}

extern "C" void kernel_launch(void* const* d_in, const int* in_sizes, int n_in,
                              void* d_out, int out_size) {
    const float* x   = (const float*)d_in[0];
    const float* emb = (const float*)d_in[1];
    float* out = (float*)d_out;
    const int B = in_sizes[0] / 3;

    // reset sync counters (graph-capturable memset node; no allocation)
    void* sp = nullptr;
    cudaGetSymbolAddress(&sp, g_sync);
    cudaMemsetAsync(sp, 0, 2 * sizeof(unsigned), 0);

    const int threads = 256;
    const int blocks = (B + threads - 1) / threads;   // 3907 >= PRE_BLOCKS
    hashenc_fused<<<blocks, threads>>>(x, emb, out, B);
}

// round 15
// speedup vs baseline: 1.0075x; 1.0075x over previous
#include <cuda_runtime.h>
#include <cuda_fp16.h>
#include <cstdint>

#define N_LEVELS 16
#define LOG2_T 19
#define HASH_MASK ((1u << LOG2_T) - 1u)
#define P0 73856093u
#define P1 19349663u
#define P2 83492791u

// floor(16 * 2^(l/3)) through the reference fp32 chain (verified in R1).
__device__ constexpr float c_resf[N_LEVELS] = {
    16.f, 20.f, 25.f, 32.f, 40.f, 50.f, 64.f, 80.f,
    101.f, 128.f, 161.f, 203.f, 256.f, 322.f, 406.f, 512.f
};

// Dense levels 0..8: fp16 2x2 yz-corner-block tables (16B entries).
#define N_DENSE 9
__device__ constexpr int c_sy[N_DENSE]  = {17, 21, 26, 33, 41, 51, 65, 81, 102};
__device__ constexpr int c_sx[N_DENSE]  = {289, 441, 676, 1089, 1681, 2601, 4225, 6561, 10404};
__device__ constexpr int c_OFF[N_DENSE] = {
    0, 5202, 14904, 33156, 70182, 140784, 276036, 554886, 1092888
};
#define DENSE_TOTAL 2164500
__device__ uint4 g_dense[DENSE_TOTAL];       // 34.6 MB, L2-resident

// Corner tables: C[cx][cy][cz], dims (R+2)^3, packed fp16x2 per corner.
__device__ constexpr int c_cd[N_DENSE]   = {18, 22, 27, 34, 42, 52, 66, 82, 103};
__device__ constexpr int c_COFF[N_DENSE] = {
    0, 5832, 16480, 36163, 75467, 149555, 290163, 577659, 1129027
};
#define CORNER_TOTAL 2221754
__device__ unsigned g_corner[CORNER_TOTAL];  // 8.9 MB (transient)

// sync counters: [0]=stage1 done, [1]=stage2 done. Reset per launch (memset node).
__device__ unsigned g_sync[2];

// magic-number unsigned division: exact for u < 2^22, d <= 130
constexpr unsigned long long magic(unsigned d) { return ((1ULL << 40) / d) + 1ULL; }
__device__ constexpr unsigned long long c_mcd[N_DENSE] = {
    magic(18), magic(22), magic(27), magic(34), magic(42),
    magic(52), magic(66), magic(82), magic(103)
};
__device__ constexpr unsigned long long c_msy[N_DENSE] = {
    magic(17), magic(21), magic(26), magic(33), magic(41),
    magic(51), magic(65), magic(81), magic(102)
};
__device__ __forceinline__ unsigned mdiv(unsigned u, unsigned long long M) {
    return (unsigned)(((unsigned long long)u * M) >> 40);
}

__device__ __forceinline__ unsigned pack_h2(float a, float b) {
    __half2 h = __floats2half2_rn(a, b);
    return *reinterpret_cast<unsigned*>(&h);
}

__device__ __forceinline__ unsigned poll_cg(const unsigned* p) {
    unsigned v;
    asm volatile("ld.global.cg.u32 %0, [%1];" : "=r"(v) : "l"(p));
    return v;
}

// One prepass block per SM: all 148 are in wave 1 at any occupancy >= 1.
#define PRE_BLOCKS 148
#define PRE_THREADS (PRE_BLOCKS * 256)

__global__ void __launch_bounds__(256, 3) hashenc_fused(
    const float* __restrict__ x,
    const float* __restrict__ emb,
    float* __restrict__ out,
    int B)
{
    const int tidb = threadIdx.x;

    // ================= inline prepass (blocks 0..147) =================
    if (blockIdx.x < PRE_BLOCKS) {
        const unsigned base = blockIdx.x * 256u + (unsigned)tidb;

        // ---- stage 1: gather each corner once (batches of 4 for MLP) ----
        for (unsigned b0 = base; b0 < CORNER_TOTAL; b0 += 4u * PRE_THREADS) {
            unsigned hh[4]; int lv[4]; bool ok[4];
            #pragma unroll
            for (int k = 0; k < 4; k++) {
                unsigned idx = b0 + (unsigned)k * PRE_THREADS;
                ok[k] = (idx < CORNER_TOTAL);
                unsigned ci = ok[k] ? idx : 0u;
                int l = 0;
                #pragma unroll
                for (int m = 1; m < N_DENSE; m++)
                    if (ci >= (unsigned)c_COFF[m]) l = m;
                unsigned loc = ci - (unsigned)c_COFF[l];
                unsigned t  = mdiv(loc, c_mcd[l]);
                unsigned cz = loc - t * (unsigned)c_cd[l];
                unsigned cx = mdiv(t, c_mcd[l]);
                unsigned cy = t - cx * (unsigned)c_cd[l];
                hh[k] = ((cx * P0) ^ (cy * P1) ^ (cz * P2)) & HASH_MASK;
                lv[k] = l;
            }
            float2 e[4];
            #pragma unroll
            for (int k = 0; k < 4; k++)
                e[k] = __ldg((const float2*)emb + ((size_t)lv[k] << LOG2_T) + hh[k]);
            #pragma unroll
            for (int k = 0; k < 4; k++)
                if (ok[k])
                    g_corner[b0 + (unsigned)k * PRE_THREADS] = pack_h2(e[k].x, e[k].y);
        }

        __threadfence();
        __syncthreads();
        if (tidb == 0) {
            atomicAdd(&g_sync[0], 1u);
            while (poll_cg(&g_sync[0]) < PRE_BLOCKS) __nanosleep(64);
        }
        __syncthreads();
        __threadfence();

        // ---- stage 2: assemble 2x2 yz-blocks ----
        for (unsigned b0 = base; b0 < DENSE_TOTAL; b0 += 4u * PRE_THREADS) {
            unsigned cb[4], dd[4]; const unsigned* Cb[4]; bool ok[4];
            #pragma unroll
            for (int k = 0; k < 4; k++) {
                unsigned idx = b0 + (unsigned)k * PRE_THREADS;
                ok[k] = (idx < DENSE_TOTAL);
                unsigned ci = ok[k] ? idx : 0u;
                int l = 0;
                #pragma unroll
                for (int m = 1; m < N_DENSE; m++)
                    if (ci >= (unsigned)c_OFF[m]) l = m;
                unsigned loc = ci - (unsigned)c_OFF[l];
                unsigned sy = (unsigned)c_sy[l];
                unsigned t  = mdiv(loc, c_msy[l]);
                unsigned bz = loc - t * sy;
                unsigned cx = mdiv(t, c_msy[l]);
                unsigned by = t - cx * sy;
                unsigned d = (unsigned)c_cd[l];
                dd[k] = d;
                Cb[k] = g_corner + c_COFF[l];
                cb[k] = (cx * d + by) * d + bz;
            }
            uint4 q[4];
            #pragma unroll
            for (int k = 0; k < 4; k++) {
                q[k].x = __ldg(Cb[k] + cb[k]);
                q[k].y = __ldg(Cb[k] + cb[k] + 1);
                q[k].z = __ldg(Cb[k] + cb[k] + dd[k]);
                q[k].w = __ldg(Cb[k] + cb[k] + dd[k] + 1);
            }
            #pragma unroll
            for (int k = 0; k < 4; k++)
                if (ok[k]) g_dense[b0 + (unsigned)k * PRE_THREADS] = q[k];
        }

        __threadfence();
        __syncthreads();
        if (tidb == 0) atomicAdd(&g_sync[1], 1u);
    }

    // ================= main work =================
    const int lane = tidb & 31;
    const int warp = tidb >> 5;
    const int i = blockIdx.x * 256 + tidb;
    const int warpBase = i - lane;
    if (warpBase >= B) return;
    const bool active = (i < B);
    const int ii = active ? i : (B - 1);

    float px = x[3 * ii + 0];
    float py = x[3 * ii + 1];
    float pz = x[3 * ii + 2];
    px = fminf(fmaxf(px, -1.0f), 1.0f);
    py = fminf(fmaxf(py, -1.0f), 1.0f);
    pz = fminf(fmaxf(pz, -1.0f), 1.0f);

    float o[2 * N_LEVELS];

    // ---------- phase 1: hashed levels 9..15 (independent of g_dense) ----------
    #pragma unroll
    for (int l = N_DENSE; l < N_LEVELS; l++) {
        const float hres = 0.5f * c_resf[l];
        float tx = fmaf(px, hres, hres);
        float ty = fmaf(py, hres, hres);
        float tz = fmaf(pz, hres, hres);
        float fbx = floorf(tx), fby = floorf(ty), fbz = floorf(tz);
        int bx = (int)fbx, by = (int)fby, bz = (int)fbz;
        float wx = tx - fbx, wy = ty - fby, wz = tz - fbz;
        float wx0 = 1.0f - wx, wy0 = 1.0f - wy, wz0 = 1.0f - wz;

        unsigned hx0 = (unsigned)bx * P0, hx1 = hx0 + P0;
        unsigned hy0 = (unsigned)by * P1, hy1 = hy0 + P1;
        unsigned hz0 = (unsigned)bz * P2, hz1 = hz0 + P2;

        unsigned h0 = (hx0 ^ hy0 ^ hz0) & HASH_MASK;
        unsigned h1 = (hx0 ^ hy0 ^ hz1) & HASH_MASK;
        unsigned h2 = (hx0 ^ hy1 ^ hz0) & HASH_MASK;
        unsigned h3 = (hx0 ^ hy1 ^ hz1) & HASH_MASK;
        unsigned h4 = (hx1 ^ hy0 ^ hz0) & HASH_MASK;
        unsigned h5 = (hx1 ^ hy0 ^ hz1) & HASH_MASK;
        unsigned h6 = (hx1 ^ hy1 ^ hz0) & HASH_MASK;
        unsigned h7 = (hx1 ^ hy1 ^ hz1) & HASH_MASK;

        const float2* tbl = (const float2*)emb + ((size_t)l << LOG2_T);
        float2 e0 = __ldg(tbl + h0);
        float2 e1 = __ldg(tbl + h1);
        float2 e2 = __ldg(tbl + h2);
        float2 e3 = __ldg(tbl + h3);
        float2 e4 = __ldg(tbl + h4);
        float2 e5 = __ldg(tbl + h5);
        float2 e6 = __ldg(tbl + h6);
        float2 e7 = __ldg(tbl + h7);

        float cxy00 = wx0 * wy0;
        float cxy01 = wx0 * wy;
        float cxy10 = wx  * wy0;
        float cxy11 = wx  * wy;

        float c0 = cxy00 * wz0, c1 = cxy00 * wz;
        float c2 = cxy01 * wz0, c3 = cxy01 * wz;
        float c4 = cxy10 * wz0, c5 = cxy10 * wz;
        float c6 = cxy11 * wz0, c7 = cxy11 * wz;

        float a0, a1;
        a0 = c0 * e0.x;            a1 = c0 * e0.y;
        a0 = fmaf(c1, e1.x, a0);   a1 = fmaf(c1, e1.y, a1);
        a0 = fmaf(c2, e2.x, a0);   a1 = fmaf(c2, e2.y, a1);
        a0 = fmaf(c3, e3.x, a0);   a1 = fmaf(c3, e3.y, a1);
        a0 = fmaf(c4, e4.x, a0);   a1 = fmaf(c4, e4.y, a1);
        a0 = fmaf(c5, e5.x, a0);   a1 = fmaf(c5, e5.y, a1);
        a0 = fmaf(c6, e6.x, a0);   a1 = fmaf(c6, e6.y, a1);
        a0 = fmaf(c7, e7.x, a0);   a1 = fmaf(c7, e7.y, a1);

        o[2 * l + 0] = a0;
        o[2 * l + 1] = a1;
    }

    // ---------- wait for prepass stage 2 before touching g_dense ----------
    if (tidb == 0) {
        while (poll_cg(&g_sync[1]) < PRE_BLOCKS) __nanosleep(128);
    }
    __syncthreads();
    __threadfence();

    // ---------- phase 2: dense levels 0..8 ----------
    #pragma unroll
    for (int l = 0; l < N_DENSE; l++) {
        const float hres = 0.5f * c_resf[l];
        float tx = fmaf(px, hres, hres);
        float ty = fmaf(py, hres, hres);
        float tz = fmaf(pz, hres, hres);
        float fbx = floorf(tx), fby = floorf(ty), fbz = floorf(tz);
        int bx = (int)fbx, by = (int)fby, bz = (int)fbz;
        float wx = tx - fbx, wy = ty - fby, wz = tz - fbz;
        float wx0 = 1.0f - wx, wy0 = 1.0f - wy, wz0 = 1.0f - wz;

        const int sy = c_sy[l];
        const int sx = c_sx[l];
        const uint4* dp = g_dense + c_OFF[l];
        int base = bx * sx + by * sy + bz;
        uint4 q0 = __ldg(dp + base);
        uint4 q1 = __ldg(dp + base + sx);

        float wyz00 = wy0 * wz0;
        float wyz01 = wy0 * wz;
        float wyz10 = wy  * wz0;
        float wyz11 = wy  * wz;

        float2 f00 = __half22float2(*reinterpret_cast<__half2*>(&q0.x));
        float2 f01 = __half22float2(*reinterpret_cast<__half2*>(&q0.y));
        float2 f10 = __half22float2(*reinterpret_cast<__half2*>(&q0.z));
        float2 f11 = __half22float2(*reinterpret_cast<__half2*>(&q0.w));
        float v0x = wyz00 * f00.x;           float v0y = wyz00 * f00.y;
        v0x = fmaf(wyz01, f01.x, v0x);       v0y = fmaf(wyz01, f01.y, v0y);
        v0x = fmaf(wyz10, f10.x, v0x);       v0y = fmaf(wyz10, f10.y, v0y);
        v0x = fmaf(wyz11, f11.x, v0x);       v0y = fmaf(wyz11, f11.y, v0y);

        float2 g00 = __half22float2(*reinterpret_cast<__half2*>(&q1.x));
        float2 g01 = __half22float2(*reinterpret_cast<__half2*>(&q1.y));
        float2 g10 = __half22float2(*reinterpret_cast<__half2*>(&q1.z));
        float2 g11 = __half22float2(*reinterpret_cast<__half2*>(&q1.w));
        float v1x = wyz00 * g00.x;           float v1y = wyz00 * g00.y;
        v1x = fmaf(wyz01, g01.x, v1x);       v1y = fmaf(wyz01, g01.y, v1y);
        v1x = fmaf(wyz10, g10.x, v1x);       v1y = fmaf(wyz10, g10.y, v1y);
        v1x = fmaf(wyz11, g11.x, v1x);       v1y = fmaf(wyz11, g11.y, v1y);

        o[2 * l + 0] = fmaf(wx, v1x, wx0 * v0x);
        o[2 * l + 1] = fmaf(wx, v1y, wx0 * v0y);
    }

    // ---- coalesced output via warp-level smem transpose (deferred, batched) ----
    __shared__ float4 sbuf[8 * 32 * 9];
    float4* wb = sbuf + warp * (32 * 9);

    if (warpBase + 32 <= B) {
        #pragma unroll
        for (int s = 0; s < 8; s++)
            wb[lane * 9 + s] = make_float4(o[4*s+0], o[4*s+1], o[4*s+2], o[4*s+3]);
        __syncwarp();
        float4* ob = (float4*)out + (size_t)warpBase * 8;
        #pragma unroll
        for (int k = 0; k < 8; k++) {
            int r = k * 4 + (lane >> 3);
            int s = lane & 7;
            __stcs(ob + k * 32 + lane, wb[r * 9 + s]);   // streaming: protect L2 hot set
        }
    } else if (active) {
        float4* po = (float4*)(out + (size_t)i * (2 * N_LEVELS));
        #pragma unroll
        for (int s = 0; s < 8; s++)
            __stcs(po + s, make_float4(o[4*s+0], o[4*s+1], o[4*s+2], o[4*s+3]));
    }
}

extern "C" void kernel_launch(void* const* d_in, const int* in_sizes, int n_in,
                              void* d_out, int out_size) {
    const float* x   = (const float*)d_in[0];
    const float* emb = (const float*)d_in[1];
    float* out = (float*)d_out;
    const int B = in_sizes[0] / 3;

    // reset sync counters (graph-capturable memset node; no allocation)
    void* sp = nullptr;
    cudaGetSymbolAddress(&sp, g_sync);
    cudaMemsetAsync(sp, 0, 2 * sizeof(unsigned), 0);

    const int threads = 256;
    const int blocks = (B + threads - 1) / threads;   // 3907 >= PRE_BLOCKS
    hashenc_fused<<<blocks, threads>>>(x, emb, out, B);
}

// round 16
// speedup vs baseline: 1.0388x; 1.0311x over previous
#include <cuda_runtime.h>
#include <cuda_fp16.h>
#include <cstdint>

#define N_LEVELS 16
#define LOG2_T 19
#define HASH_MASK ((1u << LOG2_T) - 1u)
#define P0 73856093u
#define P1 19349663u
#define P2 83492791u

// floor(16 * 2^(l/3)) through the reference fp32 chain (verified in R1).
__device__ constexpr float c_resf[N_LEVELS] = {
    16.f, 20.f, 25.f, 32.f, 40.f, 50.f, 64.f, 80.f,
    101.f, 128.f, 161.f, 203.f, 256.f, 322.f, 406.f, 512.f
};

// Dense levels 0..8: fp16 2x2 yz-corner-block tables (16B entries).
#define N_DENSE 9
__device__ constexpr int c_sy[N_DENSE]  = {17, 21, 26, 33, 41, 51, 65, 81, 102};
__device__ constexpr int c_sx[N_DENSE]  = {289, 441, 676, 1089, 1681, 2601, 4225, 6561, 10404};
__device__ constexpr int c_OFF[N_DENSE] = {
    0, 5202, 14904, 33156, 70182, 140784, 276036, 554886, 1092888
};
#define DENSE_TOTAL 2164500
__device__ uint4 g_dense[DENSE_TOTAL];       // 34.6 MB, L2-resident

// Corner tables: C[cx][cy][cz], dims (R+2)^3, packed fp16x2 per corner.
__device__ constexpr int c_cd[N_DENSE]   = {18, 22, 27, 34, 42, 52, 66, 82, 103};
__device__ constexpr int c_COFF[N_DENSE] = {
    0, 5832, 16480, 36163, 75467, 149555, 290163, 577659, 1129027
};
#define CORNER_TOTAL 2221754
__device__ unsigned g_corner[CORNER_TOTAL];  // 8.9 MB (transient)

// magic-number unsigned division: exact for u < 2^22, d <= 130
constexpr unsigned long long magic(unsigned d) { return ((1ULL << 40) / d) + 1ULL; }
__device__ constexpr unsigned long long c_mcd[N_DENSE] = {
    magic(18), magic(22), magic(27), magic(34), magic(42),
    magic(52), magic(66), magic(82), magic(103)
};
__device__ constexpr unsigned long long c_msy[N_DENSE] = {
    magic(17), magic(21), magic(26), magic(33), magic(41),
    magic(51), magic(65), magic(81), magic(102)
};
__device__ __forceinline__ unsigned mdiv(unsigned u, unsigned long long M) {
    return (unsigned)(((unsigned long long)u * M) >> 40);
}

__device__ __forceinline__ unsigned pack_h2(float a, float b) {
    __half2 h = __floats2half2_rn(a, b);
    return *reinterpret_cast<unsigned*>(&h);
}

// ------- prepass stage 1: gather each corner once (1/thread, max grid —
//         empirically fastest form: sector-bandwidth bound, not MLP bound) -------
__global__ void __launch_bounds__(256) build_corners(const float* __restrict__ emb)
{
    unsigned idx = blockIdx.x * blockDim.x + threadIdx.x;
    if (idx >= CORNER_TOTAL) return;

    int l = 0;
    #pragma unroll
    for (int m = 1; m < N_DENSE; m++)
        if (idx >= (unsigned)c_COFF[m]) l = m;
    unsigned loc = idx - (unsigned)c_COFF[l];
    unsigned t  = mdiv(loc, c_mcd[l]);              // loc / d
    unsigned cz = loc - t * (unsigned)c_cd[l];
    unsigned cx = mdiv(t, c_mcd[l]);                // t / d
    unsigned cy = t - cx * (unsigned)c_cd[l];

    unsigned h = ((cx * P0) ^ (cy * P1) ^ (cz * P2)) & HASH_MASK;
    const float2* tbl = (const float2*)emb + ((size_t)l << LOG2_T);
    float2 e = __ldg(tbl + h);
    g_corner[idx] = pack_h2(e.x, e.y);
}

// ------- prepass stage 2: assemble 2x2 yz-blocks (4/thread, coalesced) -------
#define S2_K 4
__global__ void __launch_bounds__(256) build_blocks()
{
    const unsigned tid = blockIdx.x * blockDim.x + threadIdx.x;
    const unsigned S = gridDim.x * blockDim.x;

    unsigned cb[S2_K];
    unsigned dd[S2_K];
    const unsigned* Cb[S2_K];
    bool ok[S2_K];
    #pragma unroll
    for (int k = 0; k < S2_K; k++) {
        unsigned idx = tid + k * S;
        ok[k] = (idx < DENSE_TOTAL);
        unsigned ci = ok[k] ? idx : 0u;
        int l = 0;
        #pragma unroll
        for (int m = 1; m < N_DENSE; m++)
            if (ci >= (unsigned)c_OFF[m]) l = m;
        unsigned loc = ci - (unsigned)c_OFF[l];
        unsigned sy = (unsigned)c_sy[l];
        unsigned t  = mdiv(loc, c_msy[l]);          // loc / sy
        unsigned bz = loc - t * sy;
        unsigned cx = mdiv(t, c_msy[l]);            // t / sy
        unsigned by = t - cx * sy;
        unsigned d = (unsigned)c_cd[l];
        dd[k] = d;
        Cb[k] = g_corner + c_COFF[l];
        cb[k] = (cx * d + by) * d + bz;
    }

    uint4 q[S2_K];
    #pragma unroll
    for (int k = 0; k < S2_K; k++) {
        q[k].x = __ldg(Cb[k] + cb[k]);
        q[k].y = __ldg(Cb[k] + cb[k] + 1);
        q[k].z = __ldg(Cb[k] + cb[k] + dd[k]);
        q[k].w = __ldg(Cb[k] + cb[k] + dd[k] + 1);
    }

    #pragma unroll
    for (int k = 0; k < S2_K; k++)
        if (ok[k])
            g_dense[tid + k * S] = q[k];
}

// ================= main kernel (proven body, 282.7us = L1 wavefront floor) =================
__global__ void __launch_bounds__(256) hashenc_kernel(
    const float* __restrict__ x,
    const float* __restrict__ emb,
    float* __restrict__ out,
    int B)
{
    const int lane = threadIdx.x & 31;
    const int warp = threadIdx.x >> 5;
    const int i = blockIdx.x * blockDim.x + threadIdx.x;
    const int warpBase = i - lane;
    if (warpBase >= B) return;
    const bool active = (i < B);
    const int ii = active ? i : (B - 1);

    float px = x[3 * ii + 0];
    float py = x[3 * ii + 1];
    float pz = x[3 * ii + 2];
    px = fminf(fmaxf(px, -1.0f), 1.0f);
    py = fminf(fmaxf(py, -1.0f), 1.0f);
    pz = fminf(fmaxf(pz, -1.0f), 1.0f);

    float o[2 * N_LEVELS];

    #pragma unroll
    for (int l = 0; l < N_LEVELS; l++) {
        // fast cell/weight math (trilinear continuity: 1-ulp floor
        // disagreements vs reference perturb output by ~1e-9)
        const float hres = 0.5f * c_resf[l];
        float tx = fmaf(px, hres, hres);
        float ty = fmaf(py, hres, hres);
        float tz = fmaf(pz, hres, hres);
        float fbx = floorf(tx), fby = floorf(ty), fbz = floorf(tz);
        int bx = (int)fbx, by = (int)fby, bz = (int)fbz;
        float wx = tx - fbx, wy = ty - fby, wz = tz - fbz;

        float wx0 = 1.0f - wx;
        float wy0 = 1.0f - wy;
        float wz0 = 1.0f - wz;

        float a0, a1;

        if (l < N_DENSE) {
            // dense fp16 2x2-block path: 2x LDG.128
            const int sy = c_sy[l];
            const int sx = c_sx[l];
            const uint4* dp = g_dense + c_OFF[l];
            int base = bx * sx + by * sy + bz;
            uint4 q0 = __ldg(dp + base);
            uint4 q1 = __ldg(dp + base + sx);

            float wyz00 = wy0 * wz0;
            float wyz01 = wy0 * wz;
            float wyz10 = wy  * wz0;
            float wyz11 = wy  * wz;

            float2 f00 = __half22float2(*reinterpret_cast<__half2*>(&q0.x));
            float2 f01 = __half22float2(*reinterpret_cast<__half2*>(&q0.y));
            float2 f10 = __half22float2(*reinterpret_cast<__half2*>(&q0.z));
            float2 f11 = __half22float2(*reinterpret_cast<__half2*>(&q0.w));
            float v0x = wyz00 * f00.x;           float v0y = wyz00 * f00.y;
            v0x = fmaf(wyz01, f01.x, v0x);       v0y = fmaf(wyz01, f01.y, v0y);
            v0x = fmaf(wyz10, f10.x, v0x);       v0y = fmaf(wyz10, f10.y, v0y);
            v0x = fmaf(wyz11, f11.x, v0x);       v0y = fmaf(wyz11, f11.y, v0y);

            float2 g00 = __half22float2(*reinterpret_cast<__half2*>(&q1.x));
            float2 g01 = __half22float2(*reinterpret_cast<__half2*>(&q1.y));
            float2 g10 = __half22float2(*reinterpret_cast<__half2*>(&q1.z));
            float2 g11 = __half22float2(*reinterpret_cast<__half2*>(&q1.w));
            float v1x = wyz00 * g00.x;           float v1y = wyz00 * g00.y;
            v1x = fmaf(wyz01, g01.x, v1x);       v1y = fmaf(wyz01, g01.y, v1y);
            v1x = fmaf(wyz10, g10.x, v1x);       v1y = fmaf(wyz10, g10.y, v1y);
            v1x = fmaf(wyz11, g11.x, v1x);       v1y = fmaf(wyz11, g11.y, v1y);

            a0 = fmaf(wx, v1x, wx0 * v0x);
            a1 = fmaf(wx, v1y, wx0 * v0y);
        } else {
            // hashed fp32 path: 8x LDG.64
            unsigned hx0 = (unsigned)bx * P0, hx1 = hx0 + P0;
            unsigned hy0 = (unsigned)by * P1, hy1 = hy0 + P1;
            unsigned hz0 = (unsigned)bz * P2, hz1 = hz0 + P2;

            unsigned h0 = (hx0 ^ hy0 ^ hz0) & HASH_MASK;
            unsigned h1 = (hx0 ^ hy0 ^ hz1) & HASH_MASK;
            unsigned h2 = (hx0 ^ hy1 ^ hz0) & HASH_MASK;
            unsigned h3 = (hx0 ^ hy1 ^ hz1) & HASH_MASK;
            unsigned h4 = (hx1 ^ hy0 ^ hz0) & HASH_MASK;
            unsigned h5 = (hx1 ^ hy0 ^ hz1) & HASH_MASK;
            unsigned h6 = (hx1 ^ hy1 ^ hz0) & HASH_MASK;
            unsigned h7 = (hx1 ^ hy1 ^ hz1) & HASH_MASK;

            const float2* tbl = (const float2*)emb + ((size_t)l << LOG2_T);
            float2 e0 = __ldg(tbl + h0);
            float2 e1 = __ldg(tbl + h1);
            float2 e2 = __ldg(tbl + h2);
            float2 e3 = __ldg(tbl + h3);
            float2 e4 = __ldg(tbl + h4);
            float2 e5 = __ldg(tbl + h5);
            float2 e6 = __ldg(tbl + h6);
            float2 e7 = __ldg(tbl + h7);

            float cxy00 = wx0 * wy0;
            float cxy01 = wx0 * wy;
            float cxy10 = wx  * wy0;
            float cxy11 = wx  * wy;

            float c0 = cxy00 * wz0, c1 = cxy00 * wz;
            float c2 = cxy01 * wz0, c3 = cxy01 * wz;
            float c4 = cxy10 * wz0, c5 = cxy10 * wz;
            float c6 = cxy11 * wz0, c7 = cxy11 * wz;

            a0 = c0 * e0.x;            a1 = c0 * e0.y;
            a0 = fmaf(c1, e1.x, a0);   a1 = fmaf(c1, e1.y, a1);
            a0 = fmaf(c2, e2.x, a0);   a1 = fmaf(c2, e2.y, a1);
            a0 = fmaf(c3, e3.x, a0);   a1 = fmaf(c3, e3.y, a1);
            a0 = fmaf(c4, e4.x, a0);   a1 = fmaf(c4, e4.y, a1);
            a0 = fmaf(c5, e5.x, a0);   a1 = fmaf(c5, e5.y, a1);
            a0 = fmaf(c6, e6.x, a0);   a1 = fmaf(c6, e6.y, a1);
            a0 = fmaf(c7, e7.x, a0);   a1 = fmaf(c7, e7.y, a1);
        }

        o[2 * l + 0] = a0;
        o[2 * l + 1] = a1;
    }

    // ---- coalesced output via warp-level smem transpose (deferred, batched) ----
    __shared__ float4 sbuf[8 * 32 * 9];
    float4* wb = sbuf + warp * (32 * 9);

    if (warpBase + 32 <= B) {
        #pragma unroll
        for (int s = 0; s < 8; s++)
            wb[lane * 9 + s] = make_float4(o[4*s+0], o[4*s+1], o[4*s+2], o[4*s+3]);
        __syncwarp();
        float4* ob = (float4*)out + (size_t)warpBase * 8;
        #pragma unroll
        for (int k = 0; k < 8; k++) {
            int r = k * 4 + (lane >> 3);
            int s = lane & 7;
            __stcs(ob + k * 32 + lane, wb[r * 9 + s]);   // streaming: protect L2 hot set
        }
    } else if (active) {
        float4* po = (float4*)(out + (size_t)i * (2 * N_LEVELS));
        #pragma unroll
        for (int s = 0; s < 8; s++)
            __stcs(po + s, make_float4(o[4*s+0], o[4*s+1], o[4*s+2], o[4*s+3]));
    }
}

extern "C" void kernel_launch(void* const* d_in, const int* in_sizes, int n_in,
                              void* d_out, int out_size) {
    const float* x   = (const float*)d_in[0];
    const float* emb = (const float*)d_in[1];
    float* out = (float*)d_out;
    const int B = in_sizes[0] / 3;

    build_corners<<<(CORNER_TOTAL + 255) / 256, 256>>>(emb);
    const int s2_threads = (DENSE_TOTAL + S2_K - 1) / S2_K;
    build_blocks<<<(s2_threads + 255) / 256, 256>>>();

    const int threads = 256;
    const int blocks = (B + threads - 1) / threads;
    hashenc_kernel<<<blocks, threads>>>(x, emb, out, B);
}